// round 15
// baseline (speedup 1.0000x reference)
#include <cuda_runtime.h>
#include <math.h>
#include <stdint.h>

// TimeLSTMHyp: B=64, S=128, H=I=512
//  1) Precompute mobius_matvec(U_g, x): FFMA2 GEMM (exact fp32) + scaling pass (stores ||mu_g||).
//  2) ONE persistent kernel runs all 128 steps: 80 co-resident blocks, custom grid barrier.
//     GEMM phase: block j owns 32 output cols (W slice resident in smem all steps),
//                 tf32 mma m16n8k8, m-split 2 x k-split 2 across 4 warps, smem pairwise reduce.
//     elem phase: block b owns batch b; h/c state in registers; same Poincare math as R14.

#define MIN_NORM 1e-15f
#define NBLK 80

// ---------------- static device scratch ----------------
__device__ float g_mu[8192u * 2048u];   // mobius_matvec(U_g, x): [b*128+s][g*512+j] (64 MB)
__device__ float g_tmu[8192u * 4u];     // per-row per-gate ||mu_g||
__device__ float g_wbig[2560 * 512];    // tf32-rounded: rows 0..2047 gate-major W_all; 2048..2559 W_d
__device__ float g_z[64 * 2560];        // per-step gate pre-activations
__device__ float g_h[64 * 512];
__device__ float g_c[64 * 512];
__device__ unsigned g_bar_cnt;
__device__ volatile unsigned g_bar_gen;

// ---------------- helpers ----------------
__device__ __forceinline__ float artanhc(float x) {
    x = fminf(fmaxf(x, -1.0f + 1e-5f), 1.0f - 1e-5f);
    return atanhf(x);
}
__device__ __forceinline__ float clampn(float sumsq) {
    return fmaxf(sqrtf(sumsq), MIN_NORM);
}
__device__ __forceinline__ float sigm(float x) { return 1.0f / (1.0f + expf(-x)); }

__device__ __forceinline__ float cvt_tf32(float x) {
    uint32_t r;
    asm("cvt.rna.tf32.f32 %0, %1;" : "=r"(r) : "f"(x));
    return __uint_as_float(r);
}

// packed f32x2 (FFMA2) helpers — exact-fp32 precompute GEMM
__device__ __forceinline__ unsigned long long dup_f32(float x) {
    unsigned long long r;
    asm("mov.b64 %0, {%1, %1};" : "=l"(r) : "f"(x));
    return r;
}
__device__ __forceinline__ void fma_x2(unsigned long long& d, unsigned long long a, unsigned long long b) {
    asm("fma.rn.f32x2 %0, %1, %2, %0;" : "+l"(d) : "l"(a), "l"(b));
}
__device__ __forceinline__ float2 unpack_x2(unsigned long long v) {
    float2 r;
    asm("mov.b64 {%0, %1}, %2;" : "=f"(r.x), "=f"(r.y) : "l"(v));
    return r;
}

template <int N>
__device__ __forceinline__ void block_reduce_sum(float* v) {
    __shared__ float sh[N][17];
    const int lane = threadIdx.x & 31;
    const int wid  = threadIdx.x >> 5;
    #pragma unroll
    for (int i = 0; i < N; i++) {
        float x = v[i];
        #pragma unroll
        for (int o = 16; o > 0; o >>= 1) x += __shfl_xor_sync(0xffffffffu, x, o);
        if (lane == 0) sh[i][wid] = x;
    }
    __syncthreads();
    if (wid == 0) {
        const int nw = blockDim.x >> 5;
        #pragma unroll
        for (int i = 0; i < N; i++) {
            float x = (lane < nw) ? sh[i][lane] : 0.0f;
            #pragma unroll
            for (int o = 8; o > 0; o >>= 1) x += __shfl_xor_sync(0xffffffffu, x, o);
            if (lane == 0) sh[i][16] = x;
        }
    }
    __syncthreads();
    #pragma unroll
    for (int i = 0; i < N; i++) v[i] = sh[i][16];
    __syncthreads();
}

// All 80 blocks resident (1 block/SM, 80 < 148 SMs) -> spin barrier is safe.
__device__ __forceinline__ void grid_bar() {
    __threadfence();
    __syncthreads();
    if (threadIdx.x == 0) {
        unsigned g = g_bar_gen;
        if (atomicAdd(&g_bar_cnt, 1u) == NBLK - 1u) {
            atomicExch(&g_bar_cnt, 0u);
            __threadfence();
            g_bar_gen = g + 1u;
        } else {
            while (g_bar_gen == g) { __nanosleep(64); }
        }
    }
    __syncthreads();
}

// ---------------- weight rearrangement (+ tf32 rounding) + barrier reset ----------------
__global__ void prep_w(const float* __restrict__ Wall, const float* __restrict__ Wd) {
    if (blockIdx.x == 0 && threadIdx.x == 0) { g_bar_cnt = 0u; g_bar_gen = 0u; }
    int idx = blockIdx.x * blockDim.x + threadIdx.x;
    if (idx >= 2560 * 512) return;
    int m = idx >> 9, k = idx & 511;
    float v;
    if (m < 2048) {
        int g = m >> 9, jj = m & 511;
        v = Wall[jj * 2048 + (g << 9) + k];
    } else {
        v = Wd[(m - 2048) * 512 + k];
    }
    g_wbig[idx] = cvt_tf32(v);
}

// ---------------- precompute GEMM (exact fp32, FFMA2): g_mu[r][m] = sum_k X[r,k]*U_all[m,k] ----------------
__global__ void __launch_bounds__(256) gemm_pre(const float* __restrict__ A, const float* __restrict__ U) {
    __shared__ float As[16][132];
    __shared__ float Bs[16][132];
    const int bx = blockIdx.x;
    const int by = blockIdx.y;
    const int tid = threadIdx.x;
    const int lr  = tid >> 1;
    const int lc8 = (tid & 1) << 3;
    const float* Ar = A + (size_t)(by * 128 + lr) * 512 + lc8;
    const float* Ur = U + (size_t)(bx * 128 + lr) * 512 + lc8;
    const int ty = tid >> 4, tx = tid & 15;

    unsigned long long acc[4][8];
    #pragma unroll
    for (int i = 0; i < 4; i++)
        #pragma unroll
        for (int j = 0; j < 8; j++) acc[i][j] = 0ull;

    for (int k0 = 0; k0 < 512; k0 += 16) {
        float4 a0 = *(const float4*)(Ar + k0);
        float4 a1 = *(const float4*)(Ar + k0 + 4);
        float4 b0 = *(const float4*)(Ur + k0);
        float4 b1 = *(const float4*)(Ur + k0 + 4);
        __syncthreads();
        As[lc8 + 0][lr] = a0.x; As[lc8 + 1][lr] = a0.y; As[lc8 + 2][lr] = a0.z; As[lc8 + 3][lr] = a0.w;
        As[lc8 + 4][lr] = a1.x; As[lc8 + 5][lr] = a1.y; As[lc8 + 6][lr] = a1.z; As[lc8 + 7][lr] = a1.w;
        Bs[lc8 + 0][lr] = b0.x; Bs[lc8 + 1][lr] = b0.y; Bs[lc8 + 2][lr] = b0.z; Bs[lc8 + 3][lr] = b0.w;
        Bs[lc8 + 4][lr] = b1.x; Bs[lc8 + 5][lr] = b1.y; Bs[lc8 + 6][lr] = b1.z; Bs[lc8 + 7][lr] = b1.w;
        __syncthreads();
        #pragma unroll
        for (int kk = 0; kk < 16; kk++) {
            ulonglong2 apA = *(const ulonglong2*)&As[kk][ty * 8];
            ulonglong2 apB = *(const ulonglong2*)&As[kk][ty * 8 + 4];
            #pragma unroll
            for (int j = 0; j < 8; j++) {
                unsigned long long bd = dup_f32(Bs[kk][tx + 16 * j]);
                fma_x2(acc[0][j], apA.x, bd);
                fma_x2(acc[1][j], apA.y, bd);
                fma_x2(acc[2][j], apB.x, bd);
                fma_x2(acc[3][j], apB.y, bd);
            }
        }
    }
    float* C = g_mu + (size_t)(by * 128 + ty * 8) * 2048 + bx * 128 + tx;
    #pragma unroll
    for (int ip = 0; ip < 4; ip++) {
        #pragma unroll
        for (int j = 0; j < 8; j++) {
            float2 v = unpack_x2(acc[ip][j]);
            C[(size_t)(2 * ip + 0) * 2048 + j * 16] = v.x;
            C[(size_t)(2 * ip + 1) * 2048 + j * 16] = v.y;
        }
    }
}

// ---------------- scale precomputed mu + store analytic norms ----------------
__global__ void scale_mu(const float* __restrict__ X) {
    const int r = blockIdx.x;
    const int j = threadIdx.x;
    float xj = X[(size_t)r * 512 + j];
    float* mrow = g_mu + (size_t)r * 2048;
    float m0 = mrow[j], m1 = mrow[512 + j], m2 = mrow[1024 + j], m3 = mrow[1536 + j];
    float v[5] = {xj * xj, m0 * m0, m1 * m1, m2 * m2, m3 * m3};
    block_reduce_sum<5>(v);
    float xn = clampn(v[0]);
    float at = artanhc(xn);
    float n0 = clampn(v[1]); float t0 = tanhf(n0 / xn * at); mrow[j]        = t0 / n0 * m0;
    float n1 = clampn(v[2]); float t1 = tanhf(n1 / xn * at); mrow[512 + j]  = t1 / n1 * m1;
    float n2 = clampn(v[3]); float t2 = tanhf(n2 / xn * at); mrow[1024 + j] = t2 / n2 * m2;
    float n3 = clampn(v[4]); float t3 = tanhf(n3 / xn * at); mrow[1536 + j] = t3 / n3 * m3;
    if (j == 0) {
        g_tmu[r * 4 + 0] = t0; g_tmu[r * 4 + 1] = t1;
        g_tmu[r * 4 + 2] = t2; g_tmu[r * 4 + 3] = t3;
    }
}

// ---------------- persistent recurrence kernel ----------------
// smem (floats): a_s [64][516] @0 (33024) | w_s [32][516] @33024 (16512) | s_s [64][34] @49536 (2176)
#define A_OFF 0
#define W_OFF 33024
#define S_OFF 49536
#define SMEM_FLOATS 51712   // 206848 bytes

__global__ void __launch_bounds__(512, 1) persist(const float* __restrict__ ts, float* __restrict__ out) {
    extern __shared__ float sm[];
    float* a_s = sm + A_OFF;
    float* w_s = sm + W_OFF;
    float* s_s = sm + S_OFF;

    const int j    = blockIdx.x;     // 0..79: GEMM col-slice owner; 0..63 also elem batch owner
    const int tid  = threadIdx.x;
    const int w    = tid >> 5;
    const int lane = tid & 31;
    const int gid  = lane >> 2;      // 0..7
    const int tig  = lane & 3;       // 0..3
    const int col0 = j * 32;

    // Load W slice (rows 32j..32j+31) into smem once; stays for all 128 steps.
    {
        const float* Wp = g_wbig + (size_t)col0 * 512;
        #pragma unroll
        for (int i = 0; i < 8; i++) {
            int q = tid + i * 512;           // float4 index 0..4095
            int r = q >> 7, c4 = (q & 127) << 2;
            *(float4*)&w_s[r * 516 + c4] = *(const float4*)(Wp + (size_t)r * 512 + c4);
        }
    }

    // elem state lives in registers (block b owns batch b)
    float h_reg = 0.0f, c_reg = 0.0f;
    if (j < 64) {
        h_reg = g_h[j * 512 + tid];
        c_reg = g_c[j * 512 + tid];
    }
    const float* Asrc = (j < 64) ? g_h : g_c;   // blocks 0..63: h-cols (0..2047); 64..79: c-cols (2048..2559)

    float acc[2][4][4];

    for (int step = 0; step < 128; step++) {
        // ---- stage A: full state 64x512 into smem (L2 reads, .cg to bypass incoherent L1) ----
        #pragma unroll
        for (int i = 0; i < 16; i++) {
            int q = tid + i * 512;           // float4 index 0..8191
            int r = q >> 7, c4 = (q & 127) << 2;
            float4 v = __ldcg((const float4*)(Asrc + (size_t)r * 512 + c4));
            *(float4*)&a_s[r * 516 + c4] = v;
        }
        __syncthreads();

        // ---- GEMM phase: warps 0..3, m-split 2 x k-split 2, warp tile m32n32, tf32 mma ----
        const int mhalf = w & 1, khalf = (w >> 1) & 1;
        const int m0w = mhalf * 32;
        if (w < 4) {
            #pragma unroll
            for (int mt = 0; mt < 2; mt++)
                #pragma unroll
                for (int nt = 0; nt < 4; nt++)
                    #pragma unroll
                    for (int p = 0; p < 4; p++) acc[mt][nt][p] = 0.0f;

            const int kbase = khalf * 256;
            #pragma unroll 4
            for (int ks = 0; ks < 32; ks++) {
                const int k0 = kbase + ks * 8;
                uint32_t bf0[4], bf1[4];
                #pragma unroll
                for (int nt = 0; nt < 4; nt++) {
                    const int br = (8 * nt + gid) * 516 + k0 + tig;
                    bf0[nt] = __float_as_uint(w_s[br]);
                    bf1[nt] = __float_as_uint(w_s[br + 4]);
                }
                #pragma unroll
                for (int mt = 0; mt < 2; mt++) {
                    const int rb = (m0w + 16 * mt + gid) * 516 + k0 + tig;
                    uint32_t a0 = __float_as_uint(a_s[rb]);
                    uint32_t a2 = __float_as_uint(a_s[rb + 4]);
                    uint32_t a1 = __float_as_uint(a_s[rb + 8 * 516]);
                    uint32_t a3 = __float_as_uint(a_s[rb + 8 * 516 + 4]);
                    #pragma unroll
                    for (int nt = 0; nt < 4; nt++) {
                        asm volatile(
                            "mma.sync.aligned.m16n8k8.row.col.f32.tf32.tf32.f32 "
                            "{%0,%1,%2,%3}, {%4,%5,%6,%7}, {%8,%9}, {%0,%1,%2,%3};"
                            : "+f"(acc[mt][nt][0]), "+f"(acc[mt][nt][1]),
                              "+f"(acc[mt][nt][2]), "+f"(acc[mt][nt][3])
                            : "r"(a0), "r"(a1), "r"(a2), "r"(a3), "r"(bf0[nt]), "r"(bf1[nt]));
                    }
                }
            }
            // k-half 1 publishes partials to smem scratch
            if (khalf == 1) {
                #pragma unroll
                for (int mt = 0; mt < 2; mt++)
                    #pragma unroll
                    for (int nt = 0; nt < 4; nt++) {
                        const int r0 = m0w + 16 * mt + gid;
                        const int cc = 8 * nt + 2 * tig;
                        *(float2*)&s_s[r0 * 34 + cc]       = make_float2(acc[mt][nt][0], acc[mt][nt][1]);
                        *(float2*)&s_s[(r0 + 8) * 34 + cc] = make_float2(acc[mt][nt][2], acc[mt][nt][3]);
                    }
            }
        }
        __syncthreads();
        // warps 0,1 (khalf 0) combine and write z
        if (w < 2) {
            #pragma unroll
            for (int mt = 0; mt < 2; mt++)
                #pragma unroll
                for (int nt = 0; nt < 4; nt++) {
                    const int r0 = m0w + 16 * mt + gid;
                    const int cc = 8 * nt + 2 * tig;
                    float2 p = *(const float2*)&s_s[r0 * 34 + cc];
                    float2 q = *(const float2*)&s_s[(r0 + 8) * 34 + cc];
                    __stcg((float2*)&g_z[(size_t)r0 * 2560 + col0 + cc],
                           make_float2(acc[mt][nt][0] + p.x, acc[mt][nt][1] + p.y));
                    __stcg((float2*)&g_z[(size_t)(r0 + 8) * 2560 + col0 + cc],
                           make_float2(acc[mt][nt][2] + q.x, acc[mt][nt][3] + q.y));
                }
        }

        grid_bar();   // z complete & visible

        // ---- elem phase: block b = j handles batch b ----
        if (j < 64) {
            const int b = j;
            const float t = ts[b * 128 + step];
            const float cj = c_reg;
            const float hj = h_reg;

            float zg[4], mcd;
            #pragma unroll
            for (int g = 0; g < 4; g++) zg[g] = __ldcg(&g_z[(size_t)b * 2560 + g * 512 + tid]);
            mcd = __ldcg(&g_z[(size_t)b * 2560 + 2048 + tid]);

            const size_t row = (size_t)b * 128 + step;
            const float* mup = g_mu + row * 2048;
            float mug[4], tmu[4];
            #pragma unroll
            for (int g = 0; g < 4; g++) { mug[g] = mup[g * 512 + tid]; tmu[g] = g_tmu[row * 4 + g]; }

            // R1
            float r1[11] = {cj * cj, hj * hj, mcd * mcd,
                            zg[0] * zg[0], zg[1] * zg[1], zg[2] * zg[2], zg[3] * zg[3],
                            zg[0] * mug[0], zg[1] * mug[1], zg[2] * mug[2], zg[3] * mug[3]};
            block_reduce_sum<11>(r1);
            const float c2 = r1[0];
            const float cn = clampn(c2), hn = clampn(r1[1]), mcdn = clampn(r1[2]);
            const float athn = artanhc(hn);
            const float alpha = tanhf(mcdn / cn * artanhc(cn)) / mcdn;
            const float M1n = fmaxf(fabsf(alpha) * mcdn, MIN_NORM);
            const float gamma = artanhc(M1n) / M1n * alpha;
            const float T = tanhf(gamma * mcd);
            float sg[4];
            #pragma unroll
            for (int g = 0; g < 4; g++) {
                float zn = clampn(r1[3 + g]);
                float tgh = tanhf(zn / hn * athn);
                float wc = tgh / zn;
                float x2 = tgh * tgh;
                float y2 = tmu[g] * tmu[g];
                float xy = wc * r1[7 + g];
                float den = fmaxf(1.f + 2.f * xy + x2 * y2, MIN_NORM);
                sg[g] = ((1.f + 2.f * xy + y2) * wc * zg[g] + (1.f - x2) * mug[g]) / den;
            }

            // R2
            float r2[5] = {T * T, sg[0] * sg[0], sg[1] * sg[1], sg[2] * sg[2], sg[3] * sg[3]};
            block_reduce_sum<5>(r2);
            const float Tn = clampn(r2[0]);
            const float cs1n = tanhf(Tn);
            const float cs1 = cs1n / Tn * T;
            const float cs1_2 = cs1n * cs1n;
            float gate[4];
            #pragma unroll
            for (int g = 0; g < 4; g++) {
                float sn = clampn(r2[1 + g]);
                gate[g] = sigm(artanhc(sn) / sn * sg[g]);
            }
            const float gf = gate[0], gi = gate[1], go = gate[2], ctm = gate[3];
            out[row * 512 + tid] = go;

            // R3
            const float ict = gi * ctm;
            float r3[3] = {cs1 * cj, ctm * ctm, ict * ict};
            block_reduce_sum<3>(r3);
            const float xy1 = -r3[0];
            const float ta = fabsf(t);
            const float xn_t  = fmaxf(ta * 22.62741699796952f, MIN_NORM);
            const float wxn_t = fmaxf(ta * cs1n, MIN_NORM);
            const float cs2n = tanhf(wxn_t / xn_t * artanhc(xn_t));
            const float cs2 = cs2n / wxn_t * t * cs1;
            const float cs2sq = cs2n * cs2n;
            const float denl = fmaxf(1.f + 2.f * xy1 + cs1_2 * c2, MIN_NORM);
            const float cl = ((1.f + 2.f * xy1 + c2) * (-cs1) + (1.f - cs1_2) * cj) / denl;
            const float ctn = clampn(r3[1]), ictn = clampn(r3[2]);
            const float Pn = tanhf(ictn / ctn * artanhc(ctn));
            const float P = Pn / ictn * ict;
            const float P2s = Pn * Pn;

            // R4
            float r4[2] = {cl * cl, cl * cs2};
            block_reduce_sum<2>(r4);
            const float cln2 = r4[0], xy5 = r4[1];
            const float den5 = fmaxf(1.f + 2.f * xy5 + cln2 * cs2sq, MIN_NORM);
            const float cadj = ((1.f + 2.f * xy5 + cs2sq) * cl + (1.f - cln2) * cs2) / den5;

            // R5
            const float fca = gf * cadj;
            float r5[2] = {cadj * cadj, fca * fca};
            block_reduce_sum<2>(r5);
            const float cadjn = clampn(r5[0]), fcan = clampn(r5[1]);
            const float Qn = tanhf(fcan / cadjn * artanhc(cadjn));
            const float Q = Qn / fcan * fca;
            const float Q2 = Qn * Qn;

            // R6
            float r6[1] = {P * Q};
            block_reduce_sum<1>(r6);
            const float den7 = fmaxf(1.f + 2.f * r6[0] + P2s * Q2, MIN_NORM);
            const float cnew = ((1.f + 2.f * r6[0] + Q2) * P + (1.f - P2s) * Q) / den7;

            // R7
            const float u = tanhf(cnew);
            float r7[1] = {u * u};
            block_reduce_sum<1>(r7);
            const float un = clampn(r7[0]);
            const float en_exact = tanhf(un);
            const float e = en_exact / un * u;
            const float en = fmaxf(en_exact, MIN_NORM);

            // R8
            const float oe = go * e;
            float r8[1] = {oe * oe};
            block_reduce_sum<1>(r8);
            const float oen = clampn(r8[0]);
            const float hnew = tanhf(oen / en * artanhc(en)) / oen * oe;

            h_reg = hnew;
            c_reg = cnew;
            __stcg(&g_h[b * 512 + tid], hnew);
            __stcg(&g_c[b * 512 + tid], cnew);
            if (step == 127) {
                out[(size_t)64 * 128 * 512 + (size_t)b * 512 + tid] = hnew;
                out[(size_t)64 * 128 * 512 + (size_t)64 * 512 + (size_t)b * 512 + tid] = cnew;
            }
        }

        grid_bar();   // state published before next step's staging
    }
}

// ---------------- launch ----------------
extern "C" void kernel_launch(void* const* d_in, const int* in_sizes, int n_in,
                              void* d_out, int out_size) {
    const float* inputs = (const float*)d_in[0];
    const float* ts     = (const float*)d_in[1];
    const float* h0     = (const float*)d_in[2];
    const float* c0     = (const float*)d_in[3];
    const float* Wall   = (const float*)d_in[4];
    const float* Uall   = (const float*)d_in[5];
    const float* Wd     = (const float*)d_in[6];
    float* out = (float*)d_out;

    cudaFuncSetAttribute(persist, cudaFuncAttributeMaxDynamicSharedMemorySize,
                         SMEM_FLOATS * (int)sizeof(float));

    cudaMemcpyToSymbolAsync(g_h, h0, 64 * 512 * sizeof(float), 0, cudaMemcpyDeviceToDevice, 0);
    cudaMemcpyToSymbolAsync(g_c, c0, 64 * 512 * sizeof(float), 0, cudaMemcpyDeviceToDevice, 0);

    prep_w<<<(2560 * 512 + 255) / 256, 256>>>(Wall, Wd);
    gemm_pre<<<dim3(16, 64), 256>>>(inputs, Uall);
    scale_mu<<<8192, 512>>>(inputs);

    persist<<<NBLK, 512, SMEM_FLOATS * sizeof(float)>>>(ts, out);
}